// round 2
// baseline (speedup 1.0000x reference)
#include <cuda_runtime.h>
#include <cstdint>
#include <cstddef>

#define BB 32
#define SS 48
#define VV 32000
#define EE 512
#define HH 512
#define GG 2048

// ---------------- persistent device state (no allocations allowed) ----------------
__device__ __align__(16) float d_x[BB*EE];
__device__ __align__(16) float d_h[BB*HH];
__device__ __align__(16) float d_c[BB*HH];
__device__ __align__(16) float d_gates[BB*GG];
__device__ __align__(16) float d_logits[BB*VV];
__device__ float d_rowsub[BB];
__device__ float d_pval[BB*8];
__device__ int   d_pidx[BB*8];
__device__ int   d_active[BB];
__device__ uint2 d_keys[SS];

// ---------------- threefry2x32 (exact JAX algorithm, 20 rounds) ----------------
__device__ __forceinline__ uint2 tf2x32(unsigned k0, unsigned k1, unsigned x0, unsigned x1){
  unsigned k2 = 0x1BD11BDAu ^ k0 ^ k1;
  x0 += k0; x1 += k1;
#define TFRND(R) { x0 += x1; x1 = (x1 << (R)) | (x1 >> (32-(R))); x1 ^= x0; }
  TFRND(13) TFRND(15) TFRND(26) TFRND(6)
  x0 += k1; x1 += k2 + 1u;
  TFRND(17) TFRND(29) TFRND(16) TFRND(24)
  x0 += k2; x1 += k0 + 2u;
  TFRND(13) TFRND(15) TFRND(26) TFRND(6)
  x0 += k0; x1 += k1 + 3u;
  TFRND(17) TFRND(29) TFRND(16) TFRND(24)
  x0 += k1; x1 += k2 + 4u;
  TFRND(13) TFRND(15) TFRND(26) TFRND(6)
  x0 += k2; x1 += k0 + 5u;
#undef TFRND
  return make_uint2(x0, x1);
}

// ---------------- accurate logf (cephes-style, ~1 ulp; immune to fast-math) ----------------
__device__ __forceinline__ float acc_logf(float x){
  unsigned ix = __float_as_uint(x);
  unsigned off = ix + (0x3f800000u - 0x3f3504f3u);
  int k = ((int)(off >> 23)) - 127;
  unsigned mx = (off & 0x007fffffu) + 0x3f3504f3u;
  float f = __uint_as_float(mx) - 1.0f;
  float z = f * f;
  float p =              7.0376836292e-2f;
  p = fmaf(p, f, -1.1514610310e-1f);
  p = fmaf(p, f,  1.1676998740e-1f);
  p = fmaf(p, f, -1.2420140846e-1f);
  p = fmaf(p, f,  1.4249322787e-1f);
  p = fmaf(p, f, -1.6668057665e-1f);
  p = fmaf(p, f,  2.0000714765e-1f);
  p = fmaf(p, f, -2.4999993993e-1f);
  p = fmaf(p, f,  3.3333331174e-1f);
  float y = f * z * p;
  y = fmaf(-0.5f, z, y);
  float r = fmaf((float)k, -2.12194440e-4f, y);
  r = f + r;
  r = fmaf((float)k, 0.693359375f, r);
  return r;
}

// JAX gumbel from raw 32 bits: u = max(bitcast(bits>>9|0x3f800000)-1, tiny); g = -log(-log(u))
__device__ __forceinline__ float gumbel_bits(unsigned bits){
  float f = __uint_as_float((bits >> 9) | 0x3f800000u) - 1.0f;
  float u = fmaxf(f, 1.17549435e-38f);
  float t = -acc_logf(u);
  return -acc_logf(t);
}

// ---------------- packed f32x2 helpers ----------------
__device__ __forceinline__ void fma2(unsigned long long &acc, unsigned long long a, unsigned long long b){
  asm("fma.rn.f32x2 %0, %1, %2, %0;" : "+l"(acc) : "l"(a), "l"(b));
}
__device__ __forceinline__ unsigned long long pack2(float x, float y){
  unsigned long long r; asm("mov.b64 %0, {%1, %2};" : "=l"(r) : "f"(x), "f"(y)); return r;
}
__device__ __forceinline__ float2 unpack2(unsigned long long v){
  float2 r; asm("mov.b64 {%0, %1}, %2;" : "=f"(r.x), "=f"(r.y) : "l"(v)); return r;
}

// ---------------- init: state reset + fold-like key split ----------------
__global__ void init_kernel(const float* __restrict__ encoded){
  int gid = blockIdx.x * blockDim.x + threadIdx.x;   // 0 .. 16383
  d_x[gid] = encoded[gid];
  d_h[gid] = 0.f;
  d_c[gid] = 0.f;
  if (gid < BB) d_active[gid] = 1;
  if (gid < SS) d_keys[gid] = tf2x32(0u, 42u, 0u, (unsigned)gid);  // key(42)=(0,42)
}

// ---------------- gates: [B,4H] = x@Wi^T + h@Wh^T + bi + bh ----------------
__global__ void gates_kernel(const float* __restrict__ Wi, const float* __restrict__ Wh,
                             const float* __restrict__ bi, const float* __restrict__ bh){
  __shared__ float4 sx[EE/4];
  __shared__ float4 sh[HH/4];
  int b = blockIdx.y;
  for (int i = threadIdx.x; i < EE/4; i += 256){
    sx[i] = reinterpret_cast<const float4*>(d_x + b*EE)[i];
    sh[i] = reinterpret_cast<const float4*>(d_h + b*HH)[i];
  }
  __syncthreads();
  int j = blockIdx.x * 256 + threadIdx.x;             // 0..2047
  const float4* wi = reinterpret_cast<const float4*>(Wi + (size_t)j * EE);
  const float4* wh = reinterpret_cast<const float4*>(Wh + (size_t)j * HH);
  float a0=0.f, a1=0.f, a2=0.f, a3=0.f;
#pragma unroll 4
  for (int k = 0; k < EE/4; ++k){
    float4 w = __ldg(wi + k); float4 x = sx[k];
    a0 = fmaf(w.x, x.x, a0); a1 = fmaf(w.y, x.y, a1);
    a2 = fmaf(w.z, x.z, a2); a3 = fmaf(w.w, x.w, a3);
    float4 u = __ldg(wh + k); float4 hh = sh[k];
    a0 = fmaf(u.x, hh.x, a0); a1 = fmaf(u.y, hh.y, a1);
    a2 = fmaf(u.z, hh.z, a2); a3 = fmaf(u.w, hh.w, a3);
  }
  d_gates[b*GG + j] = (a0 + a1) + (a2 + a3) + bi[j] + bh[j];
}

// ---------------- LSTM cell (torch gate order i,f,g,o) ----------------
__global__ void cell_kernel(){
  int b = blockIdx.x, k = threadIdx.x;
  float ig = d_gates[b*GG + k];
  float fg = d_gates[b*GG + 512 + k];
  float gg = d_gates[b*GG + 1024 + k];
  float og = d_gates[b*GG + 1536 + k];
  ig = 1.f / (1.f + expf(-ig));
  fg = 1.f / (1.f + expf(-fg));
  og = 1.f / (1.f + expf(-og));
  gg = tanhf(gg);
  float c = fg * d_c[b*HH + k] + ig * gg;
  d_c[b*HH + k] = c;
  d_h[b*HH + k] = og * tanhf(c);
}

// ---------------- vocab logits: [B,V] = h@Wo^T + bo (packed f32x2 FMA) ----------------
// 125 blocks x 128 threads; each thread: 2 vocab rows x all 32 batches.
// h staged transposed in smem as batch-pairs: h2[k*16+p] = (h[2p][k], h[2p+1][k]).
__global__ void __launch_bounds__(128) logits_kernel(const float* __restrict__ Wo,
                                                     const float* __restrict__ bo){
  extern __shared__ unsigned long long h2[];          // HH*16 u64 = 64KB
  for (int idx = threadIdx.x; idx < HH*16; idx += 128){
    int k = idx >> 4, p = idx & 15;
    h2[idx] = pack2(d_h[(2*p)*HH + k], d_h[(2*p+1)*HH + k]);
  }
  __syncthreads();

  int r0 = blockIdx.x * 256 + threadIdx.x * 2;        // 2 adjacent vocab rows
  const float4* w0 = reinterpret_cast<const float4*>(Wo + (size_t)r0 * HH);
  const float4* w1 = reinterpret_cast<const float4*>(Wo + (size_t)(r0+1) * HH);

  unsigned long long acc0[16], acc1[16];
#pragma unroll
  for (int p = 0; p < 16; ++p){ acc0[p] = 0ull; acc1[p] = 0ull; }

  for (int kq = 0; kq < HH/4; ++kq){
    float4 a = __ldg(w0 + kq);
    float4 c = __ldg(w1 + kq);
    const unsigned long long* hk = h2 + (kq*4)*16;
#pragma unroll
    for (int kk = 0; kk < 4; ++kk){
      float wa = (&a.x)[kk], wc = (&c.x)[kk];
      unsigned long long pa = pack2(wa, wa);
      unsigned long long pc = pack2(wc, wc);
      const unsigned long long* hp = hk + kk*16;
#pragma unroll
      for (int p = 0; p < 16; ++p){
        unsigned long long hv = hp[p];
        fma2(acc0[p], pa, hv);
        fma2(acc1[p], pc, hv);
      }
    }
  }

  float bv0 = __ldg(bo + r0), bv1 = __ldg(bo + r0 + 1);
#pragma unroll
  for (int p = 0; p < 16; ++p){
    float2 v0 = unpack2(acc0[p]);
    float2 v1 = unpack2(acc1[p]);
    d_logits[(2*p)  *VV + r0    ] = v0.x + bv0;
    d_logits[(2*p+1)*VV + r0    ] = v0.y + bv0;
    d_logits[(2*p)  *VV + r0 + 1] = v1.x + bv1;
    d_logits[(2*p+1)*VV + r0 + 1] = v1.y + bv1;
  }
}

// ---------------- per-row max + log-sum-exp ----------------
__global__ void reduce_kernel(){
  __shared__ float red[1024];
  int b = blockIdx.x, tid = threadIdx.x;
  float m = -3.402823466e38f;
  for (int v = tid; v < VV; v += 1024) m = fmaxf(m, d_logits[b*VV + v]);
  red[tid] = m; __syncthreads();
  for (int o = 512; o > 0; o >>= 1){
    if (tid < o) red[tid] = fmaxf(red[tid], red[tid+o]);
    __syncthreads();
  }
  m = red[0]; __syncthreads();
  float s = 0.f;
  for (int v = tid; v < VV; v += 1024) s += expf(d_logits[b*VV + v] - m);
  red[tid] = s; __syncthreads();
  for (int o = 512; o > 0; o >>= 1){
    if (tid < o) red[tid] += red[tid+o];
    __syncthreads();
  }
  if (tid == 0) d_rowsub[b] = m + acc_logf(red[0]);
}

// ---------------- logp store + gumbel + partial argmax ----------------
// grid (8 slices, 32 batches) x 256 threads; slice = 4000 vocab entries.
__global__ void gumbel_kernel(float* __restrict__ out, int step){
  __shared__ float sv[256];
  __shared__ int   si[256];
  int slice = blockIdx.x, b = blockIdx.y, tid = threadIdx.x;
  uint2 key = d_keys[step];
  float rs = d_rowsub[b];
  int act = d_active[b];
  float bm = -3.402823466e38f; int bidx = 0x7fffffff;
  int v0 = slice * 4000;
  size_t obase = ((size_t)b * SS + step) * VV;
  for (int v = v0 + tid; v < v0 + 4000; v += 256){
    float lp = d_logits[b*VV + v] - rs;
    out[obase + v] = act ? lp : 0.0f;
    uint2 r = tf2x32(key.x, key.y, 0u, (unsigned)(b*VV + v));
    float sc = lp + gumbel_bits(r.x ^ r.y);
    if (sc > bm || (sc == bm && v < bidx)){ bm = sc; bidx = v; }
  }
  sv[tid] = bm; si[tid] = bidx; __syncthreads();
  for (int o = 128; o > 0; o >>= 1){
    if (tid < o){
      float ov = sv[tid+o]; int oi = si[tid+o];
      if (ov > sv[tid] || (ov == sv[tid] && oi < si[tid])){ sv[tid] = ov; si[tid] = oi; }
    }
    __syncthreads();
  }
  if (tid == 0){ d_pval[b*8 + slice] = sv[0]; d_pidx[b*8 + slice] = si[0]; }
}

// ---------------- finalize: token select, EOS mask, embed gather ----------------
__global__ void finalize_kernel(const float* __restrict__ emb){
  __shared__ int tok;
  int b = blockIdx.x, tid = threadIdx.x;
  if (tid == 0){
    float bm = d_pval[b*8]; int bi_ = d_pidx[b*8];
#pragma unroll
    for (int s2 = 1; s2 < 8; ++s2){
      float v = d_pval[b*8 + s2]; int i2 = d_pidx[b*8 + s2];
      if (v > bm || (v == bm && i2 < bi_)){ bm = v; bi_ = i2; }
    }
    tok = bi_;
    if (bi_ == VV - 2) d_active[b] = 0;     // EOS
  }
  __syncthreads();
  int t = tok;
  d_x[b*EE + tid] = emb[(size_t)t*EE + tid];
}

// ---------------- launch ----------------
extern "C" void kernel_launch(void* const* d_in, const int* in_sizes, int n_in,
                              void* d_out, int out_size){
  const float* encoded = (const float*)d_in[0];
  const float* emb     = (const float*)d_in[1];
  const float* Wi      = (const float*)d_in[2];
  const float* Wh      = (const float*)d_in[3];
  const float* bi      = (const float*)d_in[4];
  const float* bh      = (const float*)d_in[5];
  const float* Wo      = (const float*)d_in[6];
  const float* bo      = (const float*)d_in[7];
  float* out = (float*)d_out;

  cudaFuncSetAttribute(logits_kernel, cudaFuncAttributeMaxDynamicSharedMemorySize, 65536);

  init_kernel<<<64, 256>>>(encoded);
  for (int s = 0; s < SS; ++s){
    gates_kernel<<<dim3(8, 32), 256>>>(Wi, Wh, bi, bh);
    cell_kernel<<<32, 512>>>();
    logits_kernel<<<125, 128, 65536>>>(Wo, bo);
    reduce_kernel<<<32, 1024>>>();
    gumbel_kernel<<<dim3(8, 32), 256>>>(out, s);
    finalize_kernel<<<32, 512>>>(emb);
  }
}

// round 3
// speedup vs baseline: 1.0662x; 1.0662x over previous
#include <cuda_runtime.h>
#include <cstdint>
#include <cstddef>

#define BB 32
#define SS 48
#define VV 32000
#define EE 512
#define HH 512
#define GG 2048

// ---------------- persistent device state (no allocations allowed) ----------------
__device__ __align__(16) float d_x[BB*EE];
__device__ __align__(16) float d_h[BB*HH];
__device__ __align__(16) float d_c[BB*HH];
__device__ __align__(16) float d_gates[BB*GG];
__device__ __align__(16) float d_logits[BB*VV];
__device__ __align__(16) unsigned long long d_h2[HH*16];   // pair-transposed h
__device__ float d_rowsub[BB];
__device__ float d_pval[BB*8];
__device__ int   d_pidx[BB*8];
__device__ int   d_active[BB];
__device__ uint2 d_keys[SS];

// ---------------- threefry2x32 (exact JAX algorithm, 20 rounds) ----------------
__device__ __forceinline__ uint2 tf2x32(unsigned k0, unsigned k1, unsigned x0, unsigned x1){
  unsigned k2 = 0x1BD11BDAu ^ k0 ^ k1;
  x0 += k0; x1 += k1;
#define TFRND(R) { x0 += x1; x1 = (x1 << (R)) | (x1 >> (32-(R))); x1 ^= x0; }
  TFRND(13) TFRND(15) TFRND(26) TFRND(6)
  x0 += k1; x1 += k2 + 1u;
  TFRND(17) TFRND(29) TFRND(16) TFRND(24)
  x0 += k2; x1 += k0 + 2u;
  TFRND(13) TFRND(15) TFRND(26) TFRND(6)
  x0 += k0; x1 += k1 + 3u;
  TFRND(17) TFRND(29) TFRND(16) TFRND(24)
  x0 += k1; x1 += k2 + 4u;
  TFRND(13) TFRND(15) TFRND(26) TFRND(6)
  x0 += k2; x1 += k0 + 5u;
#undef TFRND
  return make_uint2(x0, x1);
}

// ---------------- accurate logf (cephes-style, ~1 ulp; immune to fast-math) ----------------
__device__ __forceinline__ float acc_logf(float x){
  unsigned ix = __float_as_uint(x);
  unsigned off = ix + (0x3f800000u - 0x3f3504f3u);
  int k = ((int)(off >> 23)) - 127;
  unsigned mx = (off & 0x007fffffu) + 0x3f3504f3u;
  float f = __uint_as_float(mx) - 1.0f;
  float z = f * f;
  float p =              7.0376836292e-2f;
  p = fmaf(p, f, -1.1514610310e-1f);
  p = fmaf(p, f,  1.1676998740e-1f);
  p = fmaf(p, f, -1.2420140846e-1f);
  p = fmaf(p, f,  1.4249322787e-1f);
  p = fmaf(p, f, -1.6668057665e-1f);
  p = fmaf(p, f,  2.0000714765e-1f);
  p = fmaf(p, f, -2.4999993993e-1f);
  p = fmaf(p, f,  3.3333331174e-1f);
  float y = f * z * p;
  y = fmaf(-0.5f, z, y);
  float r = fmaf((float)k, -2.12194440e-4f, y);
  r = f + r;
  r = fmaf((float)k, 0.693359375f, r);
  return r;
}

// JAX gumbel from raw 32 bits: u = max(bitcast(bits>>9|0x3f800000)-1, tiny); g = -log(-log(u))
__device__ __forceinline__ float gumbel_bits(unsigned bits){
  float f = __uint_as_float((bits >> 9) | 0x3f800000u) - 1.0f;
  float u = fmaxf(f, 1.17549435e-38f);
  float t = -acc_logf(u);
  return -acc_logf(t);
}

// ---------------- packed f32x2 helpers ----------------
__device__ __forceinline__ void fma2(unsigned long long &acc, unsigned long long a, unsigned long long b){
  asm("fma.rn.f32x2 %0, %1, %2, %0;" : "+l"(acc) : "l"(a), "l"(b));
}
__device__ __forceinline__ unsigned long long pack2(float x, float y){
  unsigned long long r; asm("mov.b64 %0, {%1, %2};" : "=l"(r) : "f"(x), "f"(y)); return r;
}
__device__ __forceinline__ float2 unpack2(unsigned long long v){
  float2 r; asm("mov.b64 {%0, %1}, %2;" : "=f"(r.x), "=f"(r.y) : "l"(v)); return r;
}

// ---------------- init: state reset + fold-like key split ----------------
__global__ void init_kernel(const float* __restrict__ encoded){
  int gid = blockIdx.x * blockDim.x + threadIdx.x;   // 0 .. 16383
  d_x[gid] = encoded[gid];
  d_h[gid] = 0.f;
  d_c[gid] = 0.f;
  if (gid < BB) d_active[gid] = 1;
  if (gid < SS) d_keys[gid] = tf2x32(0u, 42u, 0u, (unsigned)gid);  // key(42)=(0,42)
}

// ---------------- gates: [B,4H] = x@Wi^T + h@Wh^T + bi + bh ----------------
__global__ void gates_kernel(const float* __restrict__ Wi, const float* __restrict__ Wh,
                             const float* __restrict__ bi, const float* __restrict__ bh){
  __shared__ float4 sx[EE/4];
  __shared__ float4 sh[HH/4];
  int b = blockIdx.y;
  for (int i = threadIdx.x; i < EE/4; i += 256){
    sx[i] = reinterpret_cast<const float4*>(d_x + b*EE)[i];
    sh[i] = reinterpret_cast<const float4*>(d_h + b*HH)[i];
  }
  __syncthreads();
  int j = blockIdx.x * 256 + threadIdx.x;             // 0..2047
  const float4* wi = reinterpret_cast<const float4*>(Wi + (size_t)j * EE);
  const float4* wh = reinterpret_cast<const float4*>(Wh + (size_t)j * HH);
  float a0=0.f, a1=0.f, a2=0.f, a3=0.f;
#pragma unroll 4
  for (int k = 0; k < EE/4; ++k){
    float4 w = __ldg(wi + k); float4 x = sx[k];
    a0 = fmaf(w.x, x.x, a0); a1 = fmaf(w.y, x.y, a1);
    a2 = fmaf(w.z, x.z, a2); a3 = fmaf(w.w, x.w, a3);
    float4 u = __ldg(wh + k); float4 hh = sh[k];
    a0 = fmaf(u.x, hh.x, a0); a1 = fmaf(u.y, hh.y, a1);
    a2 = fmaf(u.z, hh.z, a2); a3 = fmaf(u.w, hh.w, a3);
  }
  d_gates[b*GG + j] = (a0 + a1) + (a2 + a3) + bi[j] + bh[j];
}

// ---------------- LSTM cell (torch gate order i,f,g,o) ----------------
// Also writes h in pair-transposed layout to d_h2 for the logits kernel:
// h2[k*16+p] = pack(h[2p][k], h[2p+1][k])
__global__ void cell_kernel(){
  int b = blockIdx.x, k = threadIdx.x;
  float ig = d_gates[b*GG + k];
  float fg = d_gates[b*GG + 512 + k];
  float gg = d_gates[b*GG + 1024 + k];
  float og = d_gates[b*GG + 1536 + k];
  ig = 1.f / (1.f + expf(-ig));
  fg = 1.f / (1.f + expf(-fg));
  og = 1.f / (1.f + expf(-og));
  gg = tanhf(gg);
  float c = fg * d_c[b*HH + k] + ig * gg;
  d_c[b*HH + k] = c;
  float hval = og * tanhf(c);
  d_h[b*HH + k] = hval;
  reinterpret_cast<unsigned*>(d_h2)[(k*16 + (b>>1))*2 + (b&1)] = __float_as_uint(hval);
}

// ---------------- vocab logits: [B,V] = h@Wo^T + bo (packed f32x2 FMA) ----------------
// 125 blocks x 256 threads; each thread: 1 vocab row x all 32 batches (16 f32x2 accs).
__global__ void __launch_bounds__(256) logits_kernel(const float* __restrict__ Wo,
                                                     const float* __restrict__ bo){
  extern __shared__ unsigned long long h2[];          // HH*16 u64 = 64KB
  // linear coalesced copy of the pre-transposed h (16B per thread per iter)
  {
    const ulonglong2* src = reinterpret_cast<const ulonglong2*>(d_h2);
    ulonglong2* dst = reinterpret_cast<ulonglong2*>(h2);
    for (int i = threadIdx.x; i < HH*8; i += 256) dst[i] = src[i];
  }
  __syncthreads();

  int r = blockIdx.x * 256 + threadIdx.x;             // one vocab row per thread
  const float4* w = reinterpret_cast<const float4*>(Wo + (size_t)r * HH);

  unsigned long long acc[16];
#pragma unroll
  for (int p = 0; p < 16; ++p) acc[p] = 0ull;

  for (int kq = 0; kq < HH/4; ++kq){
    float4 wv = __ldg(w + kq);
#pragma unroll
    for (int kk = 0; kk < 4; ++kk){
      float ws = (&wv.x)[kk];
      unsigned long long pw = pack2(ws, ws);
      const ulonglong2* hp = reinterpret_cast<const ulonglong2*>(h2 + (kq*4 + kk)*16);
#pragma unroll
      for (int p = 0; p < 8; ++p){
        ulonglong2 hv = hp[p];
        fma2(acc[2*p],   pw, hv.x);
        fma2(acc[2*p+1], pw, hv.y);
      }
    }
  }

  float bv = __ldg(bo + r);
#pragma unroll
  for (int p = 0; p < 16; ++p){
    float2 v = unpack2(acc[p]);
    d_logits[(2*p)  *VV + r] = v.x + bv;
    d_logits[(2*p+1)*VV + r] = v.y + bv;
  }
}

// ---------------- per-row max + log-sum-exp ----------------
__global__ void reduce_kernel(){
  __shared__ float red[1024];
  int b = blockIdx.x, tid = threadIdx.x;
  const float4* row = reinterpret_cast<const float4*>(d_logits + b*VV);
  float m = -3.402823466e38f;
  for (int v = tid; v < VV/4; v += 1024){
    float4 x = row[v];
    m = fmaxf(m, fmaxf(fmaxf(x.x, x.y), fmaxf(x.z, x.w)));
  }
  red[tid] = m; __syncthreads();
  for (int o = 512; o > 0; o >>= 1){
    if (tid < o) red[tid] = fmaxf(red[tid], red[tid+o]);
    __syncthreads();
  }
  m = red[0]; __syncthreads();
  float s = 0.f;
  for (int v = tid; v < VV/4; v += 1024){
    float4 x = row[v];
    s += expf(x.x - m) + expf(x.y - m) + expf(x.z - m) + expf(x.w - m);
  }
  red[tid] = s; __syncthreads();
  for (int o = 512; o > 0; o >>= 1){
    if (tid < o) red[tid] += red[tid+o];
    __syncthreads();
  }
  if (tid == 0) d_rowsub[b] = m + acc_logf(red[0]);
}

// ---------------- logp store + gumbel + partial argmax ----------------
// grid (8 slices, 32 batches) x 256 threads; slice = 4000 vocab entries.
__global__ void gumbel_kernel(float* __restrict__ out, int step){
  __shared__ float sv[256];
  __shared__ int   si[256];
  int slice = blockIdx.x, b = blockIdx.y, tid = threadIdx.x;
  uint2 key = d_keys[step];
  float rs = d_rowsub[b];
  int act = d_active[b];
  float bm = -3.402823466e38f; int bidx = 0x7fffffff;
  int v0 = slice * 4000;
  size_t obase = ((size_t)b * SS + step) * VV;
  for (int v = v0 + tid; v < v0 + 4000; v += 256){
    float lp = d_logits[b*VV + v] - rs;
    out[obase + v] = act ? lp : 0.0f;
    uint2 r = tf2x32(key.x, key.y, 0u, (unsigned)(b*VV + v));
    float sc = lp + gumbel_bits(r.x ^ r.y);
    if (sc > bm || (sc == bm && v < bidx)){ bm = sc; bidx = v; }
  }
  sv[tid] = bm; si[tid] = bidx; __syncthreads();
  for (int o = 128; o > 0; o >>= 1){
    if (tid < o){
      float ov = sv[tid+o]; int oi = si[tid+o];
      if (ov > sv[tid] || (ov == sv[tid] && oi < si[tid])){ sv[tid] = ov; si[tid] = oi; }
    }
    __syncthreads();
  }
  if (tid == 0){ d_pval[b*8 + slice] = sv[0]; d_pidx[b*8 + slice] = si[0]; }
}

// ---------------- finalize: token select, EOS mask, embed gather ----------------
__global__ void finalize_kernel(const float* __restrict__ emb){
  __shared__ int tok;
  int b = blockIdx.x, tid = threadIdx.x;
  if (tid == 0){
    float bm = d_pval[b*8]; int bi_ = d_pidx[b*8];
#pragma unroll
    for (int s2 = 1; s2 < 8; ++s2){
      float v = d_pval[b*8 + s2]; int i2 = d_pidx[b*8 + s2];
      if (v > bm || (v == bm && i2 < bi_)){ bm = v; bi_ = i2; }
    }
    tok = bi_;
    if (bi_ == VV - 2) d_active[b] = 0;     // EOS
  }
  __syncthreads();
  int t = tok;
  d_x[b*EE + tid] = emb[(size_t)t*EE + tid];
}

// ---------------- launch ----------------
extern "C" void kernel_launch(void* const* d_in, const int* in_sizes, int n_in,
                              void* d_out, int out_size){
  const float* encoded = (const float*)d_in[0];
  const float* emb     = (const float*)d_in[1];
  const float* Wi      = (const float*)d_in[2];
  const float* Wh      = (const float*)d_in[3];
  const float* bi      = (const float*)d_in[4];
  const float* bh      = (const float*)d_in[5];
  const float* Wo      = (const float*)d_in[6];
  const float* bo      = (const float*)d_in[7];
  float* out = (float*)d_out;

  cudaFuncSetAttribute(logits_kernel, cudaFuncAttributeMaxDynamicSharedMemorySize, 65536);

  init_kernel<<<64, 256>>>(encoded);
  for (int s = 0; s < SS; ++s){
    gates_kernel<<<dim3(8, 32), 256>>>(Wi, Wh, bi, bh);
    cell_kernel<<<32, 512>>>();
    logits_kernel<<<125, 256, 65536>>>(Wo, bo);
    reduce_kernel<<<32, 1024>>>();
    gumbel_kernel<<<dim3(8, 32), 256>>>(out, s);
    finalize_kernel<<<32, 512>>>(emb);
  }
}